// round 1
// baseline (speedup 1.0000x reference)
#include <cuda_runtime.h>
#include <math.h>

#define B_ 32
#define T_ 2048
#define D_ 512
#define U_ 512
#define R_ 32            // rows (timesteps) per score block
#define SCORE_THREADS 512

// Scratch (no allocations allowed): bias = query@W2, raw attention logits.
__device__ float g_bias[B_ * U_];
__device__ float g_scores[B_ * T_];

// ---------------------------------------------------------------------------
// Kernel 1: bias[b][u] = sum_d query[b][d] * W2[d][u]
// ---------------------------------------------------------------------------
__global__ void bias_kernel(const float* __restrict__ query,
                            const float* __restrict__ W2) {
    const int b = blockIdx.x;
    const int u = threadIdx.x;           // 512 threads = 512 u columns
    const float* q = query + b * D_;
    float acc = 0.f;
#pragma unroll 8
    for (int d = 0; d < D_; ++d)
        acc = fmaf(q[d], W2[d * U_ + u], acc);
    g_bias[b * U_ + u] = acc;
}

// ---------------------------------------------------------------------------
// Kernel 2: fused  scores[b][t] = V . tanh(value[b,t] @ W1 + bias[b])
// Block = (batch b, tile of R_ timesteps). Thread = one u column.
// value tile staged in smem; W1 streamed from L2 (read once per block).
// ---------------------------------------------------------------------------
extern "C" __global__ void __launch_bounds__(SCORE_THREADS, 2)
score_kernel(const float* __restrict__ value,
             const float* __restrict__ W1,
             const float* __restrict__ V) {
    extern __shared__ float sval[];                  // [R_][D_] = 64 KB
    __shared__ float red[R_][16];                    // warp partials

    const int b    = blockIdx.x >> 6;                // T_/R_ = 64 tiles/batch
    const int tile = blockIdx.x & 63;
    const int t0   = tile * R_;
    const int tid  = threadIdx.x;
    const int u    = tid;

    // Stage value[b, t0:t0+R_, :] into smem (coalesced global, linear smem).
    {
        const float* src = value + ((size_t)b * T_ + t0) * D_;
#pragma unroll
        for (int it = 0; it < (R_ * D_) / SCORE_THREADS; ++it) {
            int idx = it * SCORE_THREADS + tid;
            sval[idx] = src[idx];
        }
    }
    __syncthreads();

    float acc[R_];
#pragma unroll
    for (int r = 0; r < R_; ++r) acc[r] = 0.f;

    // Mainloop: for each d-quad, 4 coalesced W1 loads (L2-resident after
    // first wave) + broadcast LDS.128 of the value quad per row + 128 FFMA.
    const float* w1p = W1 + u;
#pragma unroll 2
    for (int d = 0; d < D_; d += 4) {
        const float w0 = w1p[(d + 0) * U_];
        const float w1 = w1p[(d + 1) * U_];
        const float w2 = w1p[(d + 2) * U_];
        const float w3 = w1p[(d + 3) * U_];
#pragma unroll
        for (int r = 0; r < R_; ++r) {
            float4 v = *(const float4*)&sval[r * D_ + d];
            float a = acc[r];
            a = fmaf(v.x, w0, a);
            a = fmaf(v.y, w1, a);
            a = fmaf(v.z, w2, a);
            a = fmaf(v.w, w3, a);
            acc[r] = a;
        }
    }

    // Epilogue: tanh + V-weight, reduce 512 u-lanes -> score per row.
    const float biasu = g_bias[b * U_ + u];
    const float Vu    = V[u];
    const int warp = tid >> 5;
    const int lane = tid & 31;
#pragma unroll
    for (int r = 0; r < R_; ++r) {
        float c = Vu * tanhf(acc[r] + biasu);
#pragma unroll
        for (int off = 16; off > 0; off >>= 1)
            c += __shfl_xor_sync(0xFFFFFFFFu, c, off);
        if (lane == 0) red[r][warp] = c;
    }
    __syncthreads();
    if (tid < R_) {
        float s = 0.f;
#pragma unroll
        for (int w = 0; w < 16; ++w) s += red[tid][w];
        g_scores[b * T_ + t0 + tid] = s;
    }
}

// ---------------------------------------------------------------------------
// Kernel 3: per-batch mask + softmax + argmax (first index) + gather context.
// ---------------------------------------------------------------------------
__global__ void softmax_kernel(const float* __restrict__ value,
                               const int* __restrict__ mask,
                               float* __restrict__ ctx_out,
                               float* __restrict__ a_out) {
    const int b   = blockIdx.x;
    const int tid = threadIdx.x;                     // 256 threads
    __shared__ float smax[256];
    __shared__ int   sidx[256];
    __shared__ float ssum[256];

    // Pass 1: apply mask, track max + first argmax. Store masked logit back.
    float m = -INFINITY;
    int   mi = T_;
    for (int t = tid; t < T_; t += 256) {
        float s = g_scores[b * T_ + t] +
                  (1.f - (float)mask[b * T_ + t]) * -1e20f;
        g_scores[b * T_ + t] = s;
        if (s > m) { m = s; mi = t; }
    }
    smax[tid] = m; sidx[tid] = mi;
    __syncthreads();
    for (int s = 128; s > 0; s >>= 1) {
        if (tid < s) {
            float om = smax[tid + s]; int oi = sidx[tid + s];
            if (om > smax[tid] || (om == smax[tid] && oi < sidx[tid])) {
                smax[tid] = om; sidx[tid] = oi;
            }
        }
        __syncthreads();
    }
    const float gmax = smax[0];
    const int   gidx = sidx[0];

    // Pass 2: exp + sum.
    float sum = 0.f;
    for (int t = tid; t < T_; t += 256) {
        float e = expf(g_scores[b * T_ + t] - gmax);
        a_out[b * T_ + t] = e;
        sum += e;
    }
    ssum[tid] = sum;
    __syncthreads();
    for (int s = 128; s > 0; s >>= 1) {
        if (tid < s) ssum[tid] += ssum[tid + s];
        __syncthreads();
    }
    const float inv = 1.f / ssum[0];

    // Pass 3: normalize; gather context row at argmax.
    for (int t = tid; t < T_; t += 256)
        a_out[b * T_ + t] *= inv;
    for (int d = tid; d < D_; d += 256)
        ctx_out[b * D_ + d] = value[((size_t)b * T_ + gidx) * D_ + d];
}

// ---------------------------------------------------------------------------
extern "C" void kernel_launch(void* const* d_in, const int* in_sizes, int n_in,
                              void* d_out, int out_size) {
    const float* value = (const float*)d_in[0];
    const float* query = (const float*)d_in[1];
    const int*   mask  = (const int*)d_in[2];
    const float* W1    = (const float*)d_in[3];
    const float* W2    = (const float*)d_in[4];
    const float* V     = (const float*)d_in[5];

    float* ctx = (float*)d_out;              // context [B, D]
    float* a   = (float*)d_out + B_ * D_;    // attention weights [B, T]

    cudaFuncSetAttribute(score_kernel,
                         cudaFuncAttributeMaxDynamicSharedMemorySize,
                         R_ * D_ * (int)sizeof(float));

    bias_kernel<<<B_, U_>>>(query, W2);
    score_kernel<<<B_ * (T_ / R_), SCORE_THREADS, R_ * D_ * sizeof(float)>>>(
        value, W1, V);
    softmax_kernel<<<B_, 256>>>(value, mask, ctx, a);
}

// round 4
// speedup vs baseline: 3.5354x; 3.5354x over previous
#include <cuda_runtime.h>
#include <cuda_bf16.h>
#include <math.h>
#include <stdint.h>

#define B_ 32
#define T_ 2048
#define D_ 512
#define U_ 512
#define MT 65536            // B*T rows
#define MB_ 512             // M blocks of 128
#define NB_ 4               // N blocks of 128
#define KCH 8               // k chunks of 64
#define STAGES 3
#define KSPLIT 8
#define TILE_BYTES 16384    // 128 x 64 bf16

// ---------------- scratch (static device memory only) -----------------------
// value/W1T stored TILED+SWIZZLED: 16KB tiles = the exact smem image.
__device__ __align__(128) __nv_bfloat16 g_val_hi[MT * D_];
__device__ __align__(128) __nv_bfloat16 g_val_lo[MT * D_];
__device__ __align__(128) __nv_bfloat16 g_w1t_hi[U_ * D_];
__device__ __align__(128) __nv_bfloat16 g_w1t_lo[U_ * D_];
__device__ float g_bias_part[KSPLIT][B_ * U_];
__device__ float g_part[NB_][MT];

// ---------------- PTX helpers -----------------------------------------------
__device__ __forceinline__ uint32_t smem_u32(const void* p) {
    uint32_t a;
    asm("{ .reg .u64 t; cvta.to.shared.u64 t, %1; cvt.u32.u64 %0, t; }"
        : "=r"(a) : "l"(p));
    return a;
}
__device__ __forceinline__ uint32_t sw128(uint32_t off) {
    return off ^ ((off >> 3) & 0x70);
}
#define MBAR_INIT(a, n) \
    asm volatile("mbarrier.init.shared.b64 [%0], %1;" :: "r"(a), "r"(n) : "memory")
#define MBAR_ARRIVE(a) \
    asm volatile("mbarrier.arrive.shared.b64 _, [%0];" :: "r"(a) : "memory")
#define MBAR_EXPECT_TX(a, n) \
    asm volatile("mbarrier.arrive.expect_tx.shared.b64 _, [%0], %1;" \
                 :: "r"(a), "r"(n) : "memory")
#define MBAR_WAIT(a, ph) do {                                                  \
    uint32_t _m = (a), _p = (ph), _d;                                          \
    asm volatile("{ .reg .pred p; mbarrier.try_wait.parity.acquire.cta.shared::cta.b64 p, [%1], %2; selp.b32 %0,1,0,p; }" \
                 : "=r"(_d) : "r"(_m), "r"(_p) : "memory");                    \
    if (!_d) {                                                                 \
        asm volatile("{ .reg .pred P1; WL%=: mbarrier.try_wait.parity.acquire.cta.shared::cta.b64 P1, [%0], %1, 0x989680; @P1 bra.uni WD%=; bra.uni WL%=; WD%=: }" \
                     :: "r"(_m), "r"(_p) : "memory");                          \
    }                                                                          \
} while (0)
#define BULK_G2S(dst, src, bytes, mbar)                                        \
    asm volatile("cp.async.bulk.shared::cluster.global.mbarrier::complete_tx::bytes [%0], [%1], %2, [%3];" \
                 :: "r"(dst), "l"(src), "r"(bytes), "r"(mbar) : "memory")
#define LDSM4(r, addr)                                                         \
    asm volatile("ldmatrix.sync.aligned.m8n8.x4.shared.b16 {%0,%1,%2,%3}, [%4];" \
                 : "=r"((r)[0]), "=r"((r)[1]), "=r"((r)[2]), "=r"((r)[3])      \
                 : "r"(addr))
#define MMA16816(d, a, b)                                                      \
    asm volatile("mma.sync.aligned.m16n8k16.row.col.f32.bf16.bf16.f32 "        \
                 "{%0,%1,%2,%3}, {%4,%5,%6,%7}, {%8,%9}, {%0,%1,%2,%3};"       \
                 : "+f"((d)[0]), "+f"((d)[1]), "+f"((d)[2]), "+f"((d)[3])      \
                 : "r"((a)[0]), "r"((a)[1]), "r"((a)[2]), "r"((a)[3]),         \
                   "r"((b)[0]), "r"((b)[1]))

// tanh via exp: abs err ~1e-6; saturates correctly for large |x|
__device__ __forceinline__ float tanh_fast(float x) {
    float z = __expf(2.0f * x);
    return 1.0f - __fdividef(2.0f, z + 1.0f);
}

// ---------------- kernel 1a: value fp32 -> tiled swizzled bf16 hi/lo --------
// dest tile (mb, kc): bytes [(mb*8+kc)*16384, +16384), inside: sw128(r*128+cg*16)
__global__ void convert_value(const float4* __restrict__ v4) {
    char* dhi = reinterpret_cast<char*>(g_val_hi);
    char* dlo = reinterpret_cast<char*>(g_val_lo);
    const int ngran = MT * D_ / 8;                     // 16B granules of bf16
    for (int i = blockIdx.x * blockDim.x + threadIdx.x; i < ngran;
         i += gridDim.x * blockDim.x) {
        int m  = i >> 6;                               // row
        int g8 = i & 63;                               // granule within row
        float4 a = v4[m * 128 + g8 * 2];
        float4 b = v4[m * 128 + g8 * 2 + 1];
        float f[8] = {a.x, a.y, a.z, a.w, b.x, b.y, b.z, b.w};
        uint32_t hi[4], lo[4];
#pragma unroll
        for (int j = 0; j < 4; ++j) {
            __nv_bfloat16 h0 = __float2bfloat16(f[2 * j]);
            __nv_bfloat16 h1 = __float2bfloat16(f[2 * j + 1]);
            __nv_bfloat16 l0 = __float2bfloat16(f[2 * j] - __bfloat162float(h0));
            __nv_bfloat16 l1 = __float2bfloat16(f[2 * j + 1] - __bfloat162float(h1));
            __nv_bfloat162 th = __halves2bfloat162(h0, h1);
            __nv_bfloat162 tl = __halves2bfloat162(l0, l1);
            hi[j] = *reinterpret_cast<uint32_t*>(&th);
            lo[j] = *reinterpret_cast<uint32_t*>(&tl);
        }
        int mb = m >> 7, r = m & 127;
        int kc = g8 >> 3, cg = g8 & 7;
        size_t dest = (size_t)(mb * KCH + kc) * TILE_BYTES +
                      sw128((uint32_t)(r * 128 + cg * 16));
        *reinterpret_cast<uint4*>(dhi + dest) = make_uint4(hi[0], hi[1], hi[2], hi[3]);
        *reinterpret_cast<uint4*>(dlo + dest) = make_uint4(lo[0], lo[1], lo[2], lo[3]);
    }
}

// ---------------- kernel 1b: W1 [k][u] -> transposed tiled swizzled ---------
__global__ void convert_w1t(const float* __restrict__ W1) {
    __shared__ float s[32][33];                        // s[k_local][u_local]
    const int u0 = blockIdx.x * 32, k0 = blockIdx.y * 32;
    const int tx = threadIdx.x, ty = threadIdx.y;      // (32, 4)
#pragma unroll
    for (int j = 0; j < 8; ++j)
        s[ty + 4 * j][tx] = W1[(size_t)(k0 + ty + 4 * j) * U_ + u0 + tx];
    __syncthreads();
    // thread (tx=u_local, ty=granule 0..3 of 8 k each)
    float f[8];
#pragma unroll
    for (int e = 0; e < 8; ++e) f[e] = s[ty * 8 + e][tx];
    uint32_t hi[4], lo[4];
#pragma unroll
    for (int j = 0; j < 4; ++j) {
        __nv_bfloat16 h0 = __float2bfloat16(f[2 * j]);
        __nv_bfloat16 h1 = __float2bfloat16(f[2 * j + 1]);
        __nv_bfloat16 l0 = __float2bfloat16(f[2 * j] - __bfloat162float(h0));
        __nv_bfloat16 l1 = __float2bfloat16(f[2 * j + 1] - __bfloat162float(h1));
        __nv_bfloat162 th = __halves2bfloat162(h0, h1);
        __nv_bfloat162 tl = __halves2bfloat162(l0, l1);
        hi[j] = *reinterpret_cast<uint32_t*>(&th);
        lo[j] = *reinterpret_cast<uint32_t*>(&tl);
    }
    int u = u0 + tx, kk = k0 + ty * 8;
    int nb = u >> 7, r = u & 127;
    int kc = kk >> 6, cg = (kk & 63) >> 3;
    size_t dest = (size_t)(nb * KCH + kc) * TILE_BYTES +
                  sw128((uint32_t)(r * 128 + cg * 16));
    *reinterpret_cast<uint4*>(reinterpret_cast<char*>(g_w1t_hi) + dest) =
        make_uint4(hi[0], hi[1], hi[2], hi[3]);
    *reinterpret_cast<uint4*>(reinterpret_cast<char*>(g_w1t_lo) + dest) =
        make_uint4(lo[0], lo[1], lo[2], lo[3]);
}

// ---------------- kernel 2: bias partials (split-K, deterministic) ----------
__global__ void bias_part_kernel(const float* __restrict__ q,
                                 const float* __restrict__ W2) {
    const int b = blockIdx.x, ks = blockIdx.y, u = threadIdx.x;
    const float* qb = q + b * D_;
    float acc = 0.f;
#pragma unroll 4
    for (int d = ks * (D_ / KSPLIT); d < (ks + 1) * (D_ / KSPLIT); ++d)
        acc = fmaf(qb[d], W2[(size_t)d * U_ + u], acc);
    g_bias_part[ks][b * U_ + u] = acc;
}

// ---------------- kernel 3: HMMA score GEMM + fused epilogue ----------------
// grid = MB_*NB_ = 2048.  256 threads = 8 warps (wm 0-3 x wn 0-1).
// SMEM: [0..48) mbars full/empty x3, [64..1088) sBV float2[128],
//       [1088..2112) red float[256], data @4096: 3 stages x 64KB
//       stage: AH(16K) AL(16K) BH(16K) BL(16K)
#define SM_DATA 4096
#define STG_SZ 65536
#define SMEM_TOTAL (SM_DATA + STAGES * STG_SZ)

__global__ void __launch_bounds__(256, 1)
score_mma_kernel(const float* __restrict__ Vw) {
    extern __shared__ char smem[];
    const uint32_t sb = smem_u32(smem);
    const int tid = threadIdx.x;
    const int lane = tid & 31, wid = tid >> 5;
    const int wm = wid >> 1, wn = wid & 1;

    const int mb = blockIdx.x >> 2;
    const int nb = blockIdx.x & 3;
    const int m0 = mb * 128;
    const int b  = mb >> 4;

    if (tid == 0) {
#pragma unroll
        for (int s = 0; s < STAGES; ++s) {
            MBAR_INIT(sb + s * 16, 1);        // full: 1 expect_tx arrival
            MBAR_INIT(sb + s * 16 + 8, 256);  // empty: all threads
        }
    }
    __syncthreads();

    // bias + V per local column
    float2* sBV = reinterpret_cast<float2*>(smem + 64);
    for (int i = tid; i < 128; i += 256) {
        int u = nb * 128 + i;
        float bs = 0.f;
#pragma unroll
        for (int j = 0; j < KSPLIT; ++j) bs += g_bias_part[j][b * U_ + u];
        sBV[i] = make_float2(bs, Vw[u]);
    }

    const char* srcAh = reinterpret_cast<const char*>(g_val_hi) + (size_t)mb * KCH * TILE_BYTES;
    const char* srcAl = reinterpret_cast<const char*>(g_val_lo) + (size_t)mb * KCH * TILE_BYTES;
    const char* srcBh = reinterpret_cast<const char*>(g_w1t_hi) + (size_t)nb * KCH * TILE_BYTES;
    const char* srcBl = reinterpret_cast<const char*>(g_w1t_lo) + (size_t)nb * KCH * TILE_BYTES;

    // prologue: fill all stages
    if (tid == 0) {
#pragma unroll
        for (int c = 0; c < STAGES; ++c) {
            uint32_t st = sb + SM_DATA + c * STG_SZ;
            MBAR_EXPECT_TX(sb + c * 16, 4 * TILE_BYTES);
            BULK_G2S(st,             srcAh + (size_t)c * TILE_BYTES, TILE_BYTES, sb + c * 16);
            BULK_G2S(st + 16384,     srcAl + (size_t)c * TILE_BYTES, TILE_BYTES, sb + c * 16);
            BULK_G2S(st + 32768,     srcBh + (size_t)c * TILE_BYTES, TILE_BYTES, sb + c * 16);
            BULK_G2S(st + 49152,     srcBl + (size_t)c * TILE_BYTES, TILE_BYTES, sb + c * 16);
        }
    }

    float acc[2][8][4];
#pragma unroll
    for (int mt = 0; mt < 2; ++mt)
#pragma unroll
        for (int nt = 0; nt < 8; ++nt)
#pragma unroll
            for (int e = 0; e < 4; ++e) acc[mt][nt][e] = 0.f;

    for (int c = 0; c < KCH; ++c) {
        const int s = c % STAGES;
        const uint32_t par = (uint32_t)((c / STAGES) & 1);
        MBAR_WAIT(sb + s * 16, par);                       // full

        const uint32_t aH = sb + SM_DATA + s * STG_SZ;
        const uint32_t bH = aH + 32768;
#pragma unroll
        for (int kk = 0; kk < 4; ++kk) {
            uint32_t ah[2][4], al[2][4], bh[8][2], bl[8][2];
#pragma unroll
            for (int mt = 0; mt < 2; ++mt) {
                uint32_t off = (uint32_t)((wm * 32 + mt * 16 + (lane & 15)) * 128 +
                                          kk * 32 + ((lane >> 4) & 1) * 16);
                uint32_t ad = aH + sw128(off);
                LDSM4(ah[mt], ad);
                LDSM4(al[mt], ad + 16384);
            }
#pragma unroll
            for (int p = 0; p < 4; ++p) {
                uint32_t off = (uint32_t)((wn * 64 + p * 16 + (lane & 15)) * 128 +
                                          kk * 32 + ((lane >> 4) & 1) * 16);
                uint32_t bd = bH + sw128(off);
                uint32_t r[4];
                LDSM4(r, bd);
                bh[2 * p][0] = r[0]; bh[2 * p + 1][0] = r[1];
                bh[2 * p][1] = r[2]; bh[2 * p + 1][1] = r[3];
                LDSM4(r, bd + 16384);
                bl[2 * p][0] = r[0]; bl[2 * p + 1][0] = r[1];
                bl[2 * p][1] = r[2]; bl[2 * p + 1][1] = r[3];
            }
#pragma unroll
            for (int mt = 0; mt < 2; ++mt)
#pragma unroll
                for (int nt = 0; nt < 8; ++nt) {
                    MMA16816(acc[mt][nt], ah[mt], bh[nt]);
                    MMA16816(acc[mt][nt], ah[mt], bl[nt]);
                    MMA16816(acc[mt][nt], al[mt], bh[nt]);
                }
        }
        MBAR_ARRIVE(sb + s * 16 + 8);                      // empty

        if (tid == 0 && c + STAGES < KCH) {
            MBAR_WAIT(sb + s * 16 + 8, par);               // wait consumers
            const int cn = c + STAGES;
            uint32_t st = sb + SM_DATA + s * STG_SZ;
            MBAR_EXPECT_TX(sb + s * 16, 4 * TILE_BYTES);
            BULK_G2S(st,         srcAh + (size_t)cn * TILE_BYTES, TILE_BYTES, sb + s * 16);
            BULK_G2S(st + 16384, srcAl + (size_t)cn * TILE_BYTES, TILE_BYTES, sb + s * 16);
            BULK_G2S(st + 32768, srcBh + (size_t)cn * TILE_BYTES, TILE_BYTES, sb + s * 16);
            BULK_G2S(st + 49152, srcBl + (size_t)cn * TILE_BYTES, TILE_BYTES, sb + s * 16);
        }
    }

    // epilogue: t = V[u]*tanh(c + bias[u]); reduce rows
    float* red = reinterpret_cast<float*>(smem + 1088);    // [128][2]
#pragma unroll
    for (int mt = 0; mt < 2; ++mt) {
        float p0 = 0.f, p1 = 0.f;
#pragma unroll
        for (int nt = 0; nt < 8; ++nt) {
            int nl = wn * 64 + nt * 8 + 2 * (lane & 3);
            float2 bv0 = sBV[nl], bv1 = sBV[nl + 1];
            p0 = fmaf(bv0.y, tanh_fast(acc[mt][nt][0] + bv0.x), p0);
            p0 = fmaf(bv1.y, tanh_fast(acc[mt][nt][1] + bv1.x), p0);
            p1 = fmaf(bv0.y, tanh_fast(acc[mt][nt][2] + bv0.x), p1);
            p1 = fmaf(bv1.y, tanh_fast(acc[mt][nt][3] + bv1.x), p1);
        }
        p0 += __shfl_xor_sync(0xFFFFFFFFu, p0, 1);
        p0 += __shfl_xor_sync(0xFFFFFFFFu, p0, 2);
        p1 += __shfl_xor_sync(0xFFFFFFFFu, p1, 1);
        p1 += __shfl_xor_sync(0xFFFFFFFFu, p1, 2);
        if ((lane & 3) == 0) {
            int r = wm * 32 + mt * 16 + (lane >> 2);
            red[r * 2 + wn]       = p0;
            red[(r + 8) * 2 + wn] = p1;
        }
    }
    __syncthreads();
    if (tid < 128)
        g_part[nb][m0 + tid] = red[tid * 2] + red[tid * 2 + 1];
}

// ---------------- kernel 4: mask + softmax + argmax + gather ----------------
__global__ void softmax_kernel(const float* __restrict__ value,
                               const int* __restrict__ mask,
                               float* __restrict__ ctx_out,
                               float* __restrict__ a_out) {
    const int b = blockIdx.x;
    const int tid = threadIdx.x;                  // 256
    __shared__ float smax[256];
    __shared__ int   sidx[256];
    __shared__ float ssum[256];
    __shared__ float sc[T_];

    float m = -INFINITY; int mi = T_;
    for (int t = tid; t < T_; t += 256) {
        int i = b * T_ + t;
        float s = g_part[0][i] + g_part[1][i] + g_part[2][i] + g_part[3][i] +
                  (1.f - (float)mask[i]) * -1e20f;
        sc[t] = s;
        if (s > m) { m = s; mi = t; }
    }
    smax[tid] = m; sidx[tid] = mi;
    __syncthreads();
    for (int s = 128; s > 0; s >>= 1) {
        if (tid < s) {
            float om = smax[tid + s]; int oi = sidx[tid + s];
            if (om > smax[tid] || (om == smax[tid] && oi < sidx[tid])) {
                smax[tid] = om; sidx[tid] = oi;
            }
        }
        __syncthreads();
    }
    const float gmax = smax[0];
    const int gidx = sidx[0];

    float sum = 0.f;
    for (int t = tid; t < T_; t += 256) {
        float e = expf(sc[t] - gmax);
        sc[t] = e;
        sum += e;
    }
    ssum[tid] = sum;
    __syncthreads();
    for (int s = 128; s > 0; s >>= 1) {
        if (tid < s) ssum[tid] += ssum[tid + s];
        __syncthreads();
    }
    const float inv = 1.f / ssum[0];

    for (int t = tid; t < T_; t += 256) a_out[b * T_ + t] = sc[t] * inv;
    for (int d = tid; d < D_; d += 256)
        ctx_out[b * D_ + d] = value[((size_t)b * T_ + gidx) * D_ + d];
}

// ---------------------------------------------------------------------------
extern "C" void kernel_launch(void* const* d_in, const int* in_sizes, int n_in,
                              void* d_out, int out_size) {
    const float* value = (const float*)d_in[0];
    const float* query = (const float*)d_in[1];
    const int*   mask  = (const int*)d_in[2];
    const float* W1    = (const float*)d_in[3];
    const float* W2    = (const float*)d_in[4];
    const float* V     = (const float*)d_in[5];

    float* ctx = (float*)d_out;
    float* a   = (float*)d_out + B_ * D_;

    cudaFuncSetAttribute(score_mma_kernel,
                         cudaFuncAttributeMaxDynamicSharedMemorySize, SMEM_TOTAL);

    convert_value<<<2048, 256>>>((const float4*)value);
    convert_w1t<<<dim3(U_ / 32, D_ / 32), dim3(32, 4)>>>(W1);
    bias_part_kernel<<<dim3(B_, KSPLIT), U_>>>(query, W2);
    score_mma_kernel<<<MB_ * NB_, 256, SMEM_TOTAL>>>(V);
    softmax_kernel<<<B_, 256>>>(value, mask, ctx, a);
}